// round 1
// baseline (speedup 1.0000x reference)
#include <cuda_runtime.h>
#include <cuda_bf16.h>
#include <math.h>

// ---------------------------------------------------------------------------
// Problem constants (fixed shapes for this problem)
//   x_main : [4,256,64,64]   prior : [4,256,128,128]
//   outputs: warp [4,256,64,64] then offset_feat [4,256,64,64]
// ---------------------------------------------------------------------------
#define B4      4
#define C256    256
#define HW      64
#define NPIX    (HW*HW)          // 4096
#define IMG     (C256*NPIX)      // per-batch fp32 elements (1,048,576)
#define COUT_CO 216
#define DCN_K   2304             // 256*9

// Scratch (no allocation allowed -> __device__ globals)
__device__ float g_bufA[B4*IMG];
__device__ float g_bufB[B4*IMG];
__device__ float g_co  [B4*COUT_CO*NPIX];
__device__ float g_col [B4*DCN_K*NPIX];   // im2col for DCN (151 MB)
__device__ float g_stats[B4*32*2];        // GN mean/rstd per (b,group)

// ---------------------------------------------------------------------------
// 1) bilinear half-downsample (align_corners=False, antialias=False)
//    src = 2*dst + 0.5  ->  plain 2x2 average, no edge cases at H=128->64
// ---------------------------------------------------------------------------
__global__ void resize_half_kernel(const float* __restrict__ in, float* __restrict__ out) {
    int idx = blockIdx.x * 256 + threadIdx.x;           // over 4*256*64*64
    int x = idx & 63, y = (idx >> 6) & 63, cg = idx >> 12;  // cg = b*256+c
    const float* p = in + (size_t)cg * (128 * 128);
    int yy = 2 * y, xx = 2 * x;
    out[idx] = 0.25f * (p[yy*128 + xx] + p[yy*128 + xx + 1] +
                        p[(yy+1)*128 + xx] + p[(yy+1)*128 + xx + 1]);
}

// ---------------------------------------------------------------------------
// 2) 3x3 conv, pad 1, Cin=256, Cout param (256 or 216)
//    grid: (16 tiles, ceil(Cout/32), B) ; 256 threads
//    thread = 4 oc x 8 px (2 wide x 4 tall) -> 32 accumulators
// ---------------------------------------------------------------------------
__global__ __launch_bounds__(256)
void conv3x3_kernel(const float* __restrict__ in, const float* __restrict__ w,
                    const float* __restrict__ bias, float* __restrict__ out,
                    int Cin, int Cout) {
    const int b    = blockIdx.z;
    const int ocb  = blockIdx.y;                 // * 32
    const int tile = blockIdx.x;                 // 0..15
    const int ty0  = (tile >> 2) * 16, tx0 = (tile & 3) * 16;
    const int tid  = threadIdx.x;
    const int oc_g = tid >> 5;                   // 0..7 (4 oc each)
    const int pg   = tid & 31;                   // 32 pixel groups
    const int px0  = (pg & 7) * 2, py0 = (pg >> 3) * 4;

    __shared__ float s_in[4 * 324];              // 4 ch x 18x18 (stride 18)
    __shared__ float s_w[32 * 36];               // 32 oc x (4 ch * 9)

    float acc[32];
#pragma unroll
    for (int i = 0; i < 32; i++) acc[i] = 0.f;

    const float* inb = in + (size_t)b * Cin * NPIX;
    const size_t wstride = (size_t)Cin * 9;

    for (int c0 = 0; c0 < Cin; c0 += 4) {
        __syncthreads();
        // load 4 x 18 x 18 input tile (zero padded)
        for (int t = tid; t < 4 * 324; t += 256) {
            int cl = t / 324, r = t - cl * 324;
            int yy = r / 18 - 1 + ty0;
            int xx = r % 18 - 1 + tx0;
            float v = 0.f;
            if (yy >= 0 && yy < HW && xx >= 0 && xx < HW)
                v = inb[(size_t)(c0 + cl) * NPIX + yy * HW + xx];
            s_in[t] = v;
        }
        // load 32 oc x 36 weights (r = cl*9+k is contiguous in memory)
        for (int t = tid; t < 32 * 36; t += 256) {
            int ol = t / 36, r = t - ol * 36;
            int oc = ocb * 32 + ol;
            s_w[t] = (oc < Cout) ? w[(size_t)oc * wstride + (size_t)c0 * 9 + r] : 0.f;
        }
        __syncthreads();

#pragma unroll
        for (int cl = 0; cl < 4; cl++) {
            float win[24];                       // 6 rows x 4 cols
#pragma unroll
            for (int r = 0; r < 6; r++)
#pragma unroll
                for (int cc = 0; cc < 4; cc++)
                    win[r * 4 + cc] = s_in[cl * 324 + (py0 + r) * 18 + px0 + cc];
#pragma unroll
            for (int o = 0; o < 4; o++) {
                const float* wp = &s_w[(oc_g * 4 + o) * 36 + cl * 9];
                float w0 = wp[0], w1 = wp[1], w2 = wp[2];
                float w3 = wp[3], w4 = wp[4], w5 = wp[5];
                float w6 = wp[6], w7 = wp[7], w8 = wp[8];
#pragma unroll
                for (int j = 0; j < 4; j++)
#pragma unroll
                    for (int i = 0; i < 2; i++) {
                        float s = acc[o * 8 + j * 2 + i];
                        s = fmaf(w0, win[j*4 + i    ], s);
                        s = fmaf(w1, win[j*4 + i + 1], s);
                        s = fmaf(w2, win[j*4 + i + 2], s);
                        s = fmaf(w3, win[(j+1)*4 + i    ], s);
                        s = fmaf(w4, win[(j+1)*4 + i + 1], s);
                        s = fmaf(w5, win[(j+1)*4 + i + 2], s);
                        s = fmaf(w6, win[(j+2)*4 + i    ], s);
                        s = fmaf(w7, win[(j+2)*4 + i + 1], s);
                        s = fmaf(w8, win[(j+2)*4 + i + 2], s);
                        acc[o * 8 + j * 2 + i] = s;
                    }
            }
        }
    }

#pragma unroll
    for (int o = 0; o < 4; o++) {
        int oc = ocb * 32 + oc_g * 4 + o;
        if (oc >= Cout) continue;
        float bb = bias[oc];
        float* op = out + ((size_t)b * Cout + oc) * NPIX;
#pragma unroll
        for (int j = 0; j < 4; j++)
#pragma unroll
            for (int i = 0; i < 2; i++) {
                int oy = ty0 + py0 + j, ox = tx0 + px0 + i;
                op[oy * HW + ox] = acc[o * 8 + j * 2 + i] + bb;
            }
    }
}

// ---------------------------------------------------------------------------
// 3) 1x1 conv / GEMM: out[b,oc,px] = bias[oc] + sum_k w[oc,k]*in[b,k,px]
//    Channel k < splitK reads inA, else inB (for the concat in w1a).
//    grid: (8 px-tiles of 512, Cout/32, B); 256 threads; thread = 8 oc x 8 px
// ---------------------------------------------------------------------------
__global__ __launch_bounds__(256)
void gemm_conv_kernel(const float* __restrict__ inA, const float* __restrict__ inB,
                      int splitK, int K,
                      const float* __restrict__ w, const float* __restrict__ bias,
                      float* __restrict__ out, int Cout) {
    const int b   = blockIdx.z;
    const int ocb = blockIdx.y;                  // * 32
    const int px_base = blockIdx.x * 512;
    const int tid  = threadIdx.x;
    const int oc_g = tid >> 6;                   // 0..3 (8 oc each)
    const int pxg  = tid & 63;                   // 64 groups (8 px each)

    __shared__ float s_in[8 * 512];
    __shared__ float s_w[8 * 32];                // [kk][oc_local]

    float acc[64];
#pragma unroll
    for (int i = 0; i < 64; i++) acc[i] = 0.f;

    for (int k0 = 0; k0 < K; k0 += 8) {
        __syncthreads();
        // input: 8 rows x 512 px, vectorized
        for (int t = tid; t < 8 * 128; t += 256) {
            int row = t >> 7, c4 = t & 127;
            int k = k0 + row;
            const float* src;
            if (k < splitK) src = inA + ((size_t)b * splitK + k) * NPIX;
            else            src = inB + ((size_t)b * (K - splitK) + (k - splitK)) * NPIX;
            float4 v = *(const float4*)(src + px_base + c4 * 4);
            *(float4*)&s_in[row * 512 + c4 * 4] = v;
        }
        // weights: 8 kk x 32 oc
        {
            int kk = tid >> 5, ol = tid & 31;
            int oc = ocb * 32 + ol;
            s_w[kk * 32 + ol] = (oc < Cout) ? w[(size_t)oc * K + k0 + kk] : 0.f;
        }
        __syncthreads();

#pragma unroll
        for (int kk = 0; kk < 8; kk++) {
            float wv[8], iv[8];
#pragma unroll
            for (int o = 0; o < 8; o++) wv[o] = s_w[kk * 32 + oc_g * 8 + o];
#pragma unroll
            for (int p = 0; p < 8; p++) iv[p] = s_in[kk * 512 + pxg * 8 + p];
#pragma unroll
            for (int o = 0; o < 8; o++)
#pragma unroll
                for (int p = 0; p < 8; p++)
                    acc[o * 8 + p] = fmaf(wv[o], iv[p], acc[o * 8 + p]);
        }
    }

#pragma unroll
    for (int o = 0; o < 8; o++) {
        int oc = ocb * 32 + oc_g * 8 + o;
        if (oc >= Cout) continue;
        float bb = bias[oc];
        float* op = out + ((size_t)b * Cout + oc) * NPIX + px_base + pxg * 8;
#pragma unroll
        for (int p = 0; p < 8; p++) op[p] = acc[o * 8 + p] + bb;
    }
}

// ---------------------------------------------------------------------------
// 4) GroupNorm stats (32 groups of 8 channels) : one block per (b,g)
// ---------------------------------------------------------------------------
__global__ void gn_stats_kernel(const float* __restrict__ x, float* __restrict__ stats) {
    int bg = blockIdx.x;                          // b*32+g
    const float* p = x + (size_t)bg * 32768;      // 8 ch * 4096 px, contiguous
    float s = 0.f, ss = 0.f;
    for (int i = threadIdx.x; i < 32768; i += 256) {
        float v = p[i];
        s += v;
        ss = fmaf(v, v, ss);
    }
#pragma unroll
    for (int o = 16; o > 0; o >>= 1) {
        s  += __shfl_down_sync(0xffffffffu, s, o);
        ss += __shfl_down_sync(0xffffffffu, ss, o);
    }
    __shared__ float sh[16];
    int wrp = threadIdx.x >> 5, lane = threadIdx.x & 31;
    if (lane == 0) { sh[wrp] = s; sh[wrp + 8] = ss; }
    __syncthreads();
    if (threadIdx.x == 0) {
        float S = 0.f, SS = 0.f;
#pragma unroll
        for (int i = 0; i < 8; i++) { S += sh[i]; SS += sh[i + 8]; }
        float mu  = S * (1.f / 32768.f);
        float var = SS * (1.f / 32768.f) - mu * mu;
        stats[bg * 2]     = mu;
        stats[bg * 2 + 1] = rsqrtf(var + 1e-6f);
    }
}

// ---------------------------------------------------------------------------
// 5) GN apply (affine) + SiLU, elementwise; out may alias x
// ---------------------------------------------------------------------------
__global__ void gn_apply_silu_kernel(const float* __restrict__ x, const float* __restrict__ stats,
                                     const float* __restrict__ gamma, const float* __restrict__ beta,
                                     float* __restrict__ out) {
    int idx = blockIdx.x * 256 + threadIdx.x;     // over 4*256*4096
    int cg = idx >> 12;
    int c = cg & 255;
    int bg = (cg >> 8) * 32 + (c >> 3);
    float mu = stats[bg * 2], rs = stats[bg * 2 + 1];
    float v = fmaf((x[idx] - mu) * rs, gamma[c], beta[c]);
    out[idx] = v * (1.f / (1.f + __expf(-v)));
}

// ---------------------------------------------------------------------------
// 6) 7x7 depthwise conv, pad 3 : one block per (b,c)
// ---------------------------------------------------------------------------
__global__ __launch_bounds__(256)
void dwconv7x7_kernel(const float* __restrict__ x, const float* __restrict__ w,
                      const float* __restrict__ bias, float* __restrict__ out) {
    int bc = blockIdx.x;                          // b*256+c
    int c = bc & 255;
    const float* p = x + (size_t)bc * NPIX;
    __shared__ float s[70 * 70];
    __shared__ float sw[49];
    for (int t = threadIdx.x; t < 70 * 70; t += 256) {
        int yy = t / 70 - 3, xx = t % 70 - 3;
        s[t] = (yy >= 0 && yy < HW && xx >= 0 && xx < HW) ? p[yy * HW + xx] : 0.f;
    }
    if (threadIdx.x < 49) sw[threadIdx.x] = w[c * 49 + threadIdx.x];
    float bb = bias[c];
    __syncthreads();
    for (int t = threadIdx.x; t < NPIX; t += 256) {
        int y = t >> 6, xq = t & 63;
        float a = bb;
#pragma unroll
        for (int i = 0; i < 7; i++)
#pragma unroll
            for (int j = 0; j < 7; j++)
                a = fmaf(sw[i * 7 + j], s[(y + i) * 70 + xq + j], a);
        out[(size_t)bc * NPIX + t] = a;
    }
}

// ---------------------------------------------------------------------------
// 7) DCN im2col: modulated bilinear gather -> col[b, (g*32+c)*9+k, px]
//    grid: (16 px blocks, 72 = g*9+k, B); 256 threads; thread does 32 channels
// ---------------------------------------------------------------------------
__global__ __launch_bounds__(256)
void dcn_im2col_kernel(const float* __restrict__ x, const float* __restrict__ co,
                       float* __restrict__ col) {
    const int b  = blockIdx.z;
    const int gk = blockIdx.y;
    const int g  = gk / 9, k = gk - g * 9;
    const int px = blockIdx.x * 256 + threadIdx.x;  // 0..4095
    const int y  = px >> 6, xp = px & 63;

    const float* cob = co + (size_t)b * COUT_CO * NPIX;
    float dy = cob[(size_t)(g * 18 + 2 * k)     * NPIX + px];
    float dx = cob[(size_t)(g * 18 + 2 * k + 1) * NPIX + px];
    float mv = cob[(size_t)(144 + g * 9 + k)    * NPIX + px];
    float m  = 1.f / (1.f + __expf(-mv));

    float py  = (float)(y  - 1 + k / 3) + dy;
    float pxf = (float)(xp - 1 + k % 3) + dx;
    float y0f = floorf(py), x0f = floorf(pxf);
    float wy = py - y0f, wx = pxf - x0f;
    int y0 = (int)y0f, x0 = (int)x0f;

    bool vy0 = (y0 >= 0)     && (y0 < HW);
    bool vy1 = (y0 + 1 >= 0) && (y0 + 1 < HW);
    bool vx0 = (x0 >= 0)     && (x0 < HW);
    bool vx1 = (x0 + 1 >= 0) && (x0 + 1 < HW);

    float m00 = (vy0 && vx0) ? m * (1.f - wy) * (1.f - wx) : 0.f;
    float m01 = (vy0 && vx1) ? m * (1.f - wy) * wx         : 0.f;
    float m10 = (vy1 && vx0) ? m * wy * (1.f - wx)         : 0.f;
    float m11 = (vy1 && vx1) ? m * wy * wx                 : 0.f;

    int iy0 = min(max(y0, 0), HW - 1), iy1 = min(max(y0 + 1, 0), HW - 1);
    int ix0 = min(max(x0, 0), HW - 1), ix1 = min(max(x0 + 1, 0), HW - 1);
    int i00 = iy0 * HW + ix0, i01 = iy0 * HW + ix1;
    int i10 = iy1 * HW + ix0, i11 = iy1 * HW + ix1;

    const float* xb = x + ((size_t)b * C256 + g * 32) * NPIX;
    float* colb = col + ((size_t)b * DCN_K + (size_t)(g * 32) * 9 + k) * NPIX + px;

#pragma unroll 4
    for (int c = 0; c < 32; c++) {
        const float* xc = xb + (size_t)c * NPIX;
        float v = m00 * xc[i00] + m01 * xc[i01] + m10 * xc[i10] + m11 * xc[i11];
        colb[(size_t)c * 9 * NPIX] = v;
    }
}

// ---------------------------------------------------------------------------
// Launch
// ---------------------------------------------------------------------------
extern "C" void kernel_launch(void* const* d_in, const int* in_sizes, int n_in,
                              void* d_out, int out_size) {
    const float* x_main = (const float*)d_in[0];
    const float* prior  = (const float*)d_in[1];
    const float* ds_w = (const float*)d_in[2];  const float* ds_b = (const float*)d_in[3];
    const float* w1a  = (const float*)d_in[4];  const float* b1a  = (const float*)d_in[5];
    const float* g1a  = (const float*)d_in[6];  const float* be1a = (const float*)d_in[7];
    const float* w1b  = (const float*)d_in[8];  const float* b1b  = (const float*)d_in[9];
    const float* g1b  = (const float*)d_in[10]; const float* be1b = (const float*)d_in[11];
    const float* w1c  = (const float*)d_in[12]; const float* b1c  = (const float*)d_in[13];
    const float* w2   = (const float*)d_in[14]; const float* b2   = (const float*)d_in[15];
    const float* g2   = (const float*)d_in[16]; const float* be2  = (const float*)d_in[17];
    const float* co_w = (const float*)d_in[18]; const float* co_b = (const float*)d_in[19];
    const float* dcn_w= (const float*)d_in[20]; const float* dcn_b= (const float*)d_in[21];

    float *bufA, *bufB, *coBuf, *colBuf, *stats;
    cudaGetSymbolAddress((void**)&bufA,  g_bufA);
    cudaGetSymbolAddress((void**)&bufB,  g_bufB);
    cudaGetSymbolAddress((void**)&coBuf, g_co);
    cudaGetSymbolAddress((void**)&colBuf,g_col);
    cudaGetSymbolAddress((void**)&stats, g_stats);

    float* out_warp = (float*)d_out;                  // [4,256,64,64]
    float* out_feat = out_warp + (size_t)B4 * IMG;    // [4,256,64,64]

    const int EL_BLOCKS = (B4 * IMG) / 256;           // 16384

    // 1. downsample prior -> bufB
    resize_half_kernel<<<EL_BLOCKS, 256>>>(prior, bufB);
    // 2. ds conv 3x3 -> bufA (pr)
    conv3x3_kernel<<<dim3(16, 8, B4), 256>>>(bufB, ds_w, ds_b, bufA, C256, C256);
    // 3. 1x1 conv over concat(pr, x_main) -> bufB (f)
    gemm_conv_kernel<<<dim3(8, 8, B4), 256>>>(bufA, x_main, 256, 512, w1a, b1a, bufB, C256);
    // 4. GN + SiLU (in place)
    gn_stats_kernel<<<B4 * 32, 256>>>(bufB, stats);
    gn_apply_silu_kernel<<<EL_BLOCKS, 256>>>(bufB, stats, g1a, be1a, bufB);
    // 5. 7x7 depthwise -> bufA
    dwconv7x7_kernel<<<B4 * C256, 256>>>(bufB, w1b, b1b, bufA);
    // 6. GN + SiLU (in place)
    gn_stats_kernel<<<B4 * 32, 256>>>(bufA, stats);
    gn_apply_silu_kernel<<<EL_BLOCKS, 256>>>(bufA, stats, g1b, be1b, bufA);
    // 7. 1x1 conv -> bufB
    gemm_conv_kernel<<<dim3(8, 8, B4), 256>>>(bufA, nullptr, 256, 256, w1c, b1c, bufB, C256);
    // 8. 3x3 conv (w2) -> bufA
    conv3x3_kernel<<<dim3(16, 8, B4), 256>>>(bufB, w2, b2, bufA, C256, C256);
    // 9. GN + SiLU -> offset_feat (second output)
    gn_stats_kernel<<<B4 * 32, 256>>>(bufA, stats);
    gn_apply_silu_kernel<<<EL_BLOCKS, 256>>>(bufA, stats, g2, be2, out_feat);
    // 10. co conv 3x3 (256 -> 216) -> coBuf
    conv3x3_kernel<<<dim3(16, 7, B4), 256>>>(out_feat, co_w, co_b, coBuf, C256, COUT_CO);
    // 11. DCN im2col -> colBuf
    dcn_im2col_kernel<<<dim3(16, 72, B4), 256>>>(x_main, coBuf, colBuf);
    // 12. DCN GEMM (K=2304) -> warp (first output)
    gemm_conv_kernel<<<dim3(8, 8, B4), 256>>>(colBuf, nullptr, DCN_K, DCN_K, dcn_w, dcn_b, out_warp, C256);
}